// round 11
// baseline (speedup 1.0000x reference)
#include <cuda_runtime.h>
#include <cuda_bf16.h>
#include <math.h>

#define DIM     64
#define KCB     512
#define MCHUNK  128
#define NTH     256
#define WARPS   8
#define GRID    128
#define MARGIN  3e-3f

typedef unsigned int       u32;
typedef unsigned long long u64;
typedef unsigned short     u16;

// ---------------- device scratch ----------------
__device__ float g_ET[KCB * DIM];   // transposed codebook [K][D] fp32
__device__ float g_loss;
__device__ int   g_cnt[KCB];

// ---------------- smem layout (byte offsets) ----------------
#define B_OFF    0          // [seg2][kstep4] x 512 n x 32B   = 131072
#define A_OFF    131072     // [seg2][kstep4] x 128 m x 32B   = 32768
#define STG_OFF  163840     // 8 warps x 16 rows x 66 floats  = 33792
#define ESQ_OFF  197632     // 512 f
#define XSQ_OFF  199680     // 128 f
#define BKS_OFF  200192     // 128 i
#define HIST_OFF 200704     // 512 i
#define LRED_OFF 202752     // 8 f
#define BVS_OFF  202784     // 128 f (approx best value per row)
#define FLG_OFF  203296     // 128 i (near-tie flag)
#define SMEM_BYTES 203808

__device__ __forceinline__ u32 bfpack(float a, float b) {
    __nv_bfloat16 ha = __float2bfloat16(a), hb = __float2bfloat16(b);
    u16 ua = *reinterpret_cast<u16*>(&ha), ub = *reinterpret_cast<u16*>(&hb);
    return (u32)ua | ((u32)ub << 16);
}
__device__ __forceinline__ float bf2f(__nv_bfloat16 h) { return __bfloat162float(h); }

#define MMA16816(c, a, b0v, b1v)                                              \
    asm volatile("mma.sync.aligned.m16n8k16.row.col.f32.bf16.bf16.f32 "       \
        "{%0,%1,%2,%3}, {%4,%5,%6,%7}, {%8,%9}, {%0,%1,%2,%3};"               \
        : "+f"((c)[0]), "+f"((c)[1]), "+f"((c)[2]), "+f"((c)[3])              \
        : "r"((a)[0]), "r"((a)[1]), "r"((a)[2]), "r"((a)[3]),                 \
          "r"(b0v), "r"(b1v))

// ---------------- prep ----------------
__global__ void vq_prep(const float* __restrict__ E) {
    __shared__ float t[32][33];
    const int kb = blockIdx.x * 32, db = blockIdx.y * 32;
    t[threadIdx.y][threadIdx.x] = E[(db + threadIdx.y) * KCB + kb + threadIdx.x];
    __syncthreads();
    g_ET[(kb + threadIdx.y) * DIM + db + threadIdx.x] = t[threadIdx.x][threadIdx.y];
    if (blockIdx.x == 0 && blockIdx.y == 0) {
        int id = threadIdx.y * 32 + threadIdx.x;
        if (id < KCB) g_cnt[id] = 0;
        if (id == 0)  g_loss = 0.f;
    }
}

// ---------------- main: mma.sync split-bf16 GEMM + exact rescue ---------
__global__ void __launch_bounds__(NTH, 1)
vq_main(const float* __restrict__ x,
        float* __restrict__ quant, float* __restrict__ enc,
        float* __restrict__ idxf,  float* __restrict__ dist, int nRows)
{
    extern __shared__ char SB[];
    float* esq  = (float*)(SB + ESQ_OFF);
    float* xsq  = (float*)(SB + XSQ_OFF);
    int*   bks  = (int*)  (SB + BKS_OFF);
    int*   hist = (int*)  (SB + HIST_OFF);
    float* lred = (float*)(SB + LRED_OFF);
    float* bvs  = (float*)(SB + BVS_OFF);
    int*   flg  = (int*)  (SB + FLG_OFF);

    const int tid  = threadIdx.x;
    const int lane = tid & 31;
    const int w    = tid >> 5;
    const int g    = lane >> 2;
    const int q    = lane & 3;

    const int SEGA[3] = { 0, 0, 1 };   // (H,H) (H,L) (L,H)
    const int SEGB[3] = { 0, 1, 0 };

    // ---- B planes + exact esq
#pragma unroll
    for (int j = 0; j < 2; j++) {
        const int n = tid + j * NTH;
        float f[DIM];
        const float4* er = (const float4*)(g_ET + (size_t)n * DIM);
#pragma unroll
        for (int i = 0; i < 16; i++) {
            float4 v = er[i];
            f[4*i] = v.x; f[4*i+1] = v.y; f[4*i+2] = v.z; f[4*i+3] = v.w;
        }
        float sq = 0.f;
#pragma unroll
        for (int i = 0; i < DIM; i++) sq = fmaf(f[i], f[i], sq);
        esq[n] = sq;

        float r[DIM];
#pragma unroll
        for (int i = 0; i < DIM; i++) {
            __nv_bfloat16 h = __float2bfloat16(f[i]);
            r[i] = f[i] - bf2f(h);
        }
#pragma unroll
        for (int s4 = 0; s4 < 4; s4++)
#pragma unroll
            for (int qq = 0; qq < 4; qq++) {
                const int d0 = 16 * s4 + 2 * qq;
                u64 hp = (u64)bfpack(f[d0], f[d0+1]) |
                         ((u64)bfpack(f[d0+8], f[d0+9]) << 32);
                u64 lp = (u64)bfpack(r[d0], r[d0+1]) |
                         ((u64)bfpack(r[d0+8], r[d0+9]) << 32);
                *(u64*)(SB + B_OFF + ((size_t)((0*4+s4)*KCB + n))*32 + qq*8) = hp;
                *(u64*)(SB + B_OFF + ((size_t)((1*4+s4)*KCB + n))*32 + qq*8) = lp;
            }
    }
    for (int i = tid; i < KCB; i += NTH) hist[i] = 0;
    __syncthreads();

    float lossAcc = 0.f;
    const int nChunks = nRows / MCHUNK;

    for (int chunk = blockIdx.x; chunk < nChunks; chunk += GRID) {
        const int row0 = chunk * MCHUNK;

        __syncthreads();   // prev chunk's A-frag reads done
        {
            const int row = tid >> 1, hf = tid & 1;
            const float4* xr = (const float4*)(x + (size_t)(row0 + row) * DIM) + hf * 8;
            float f[32];
#pragma unroll
            for (int i = 0; i < 8; i++) {
                float4 v = xr[i];
                f[4*i] = v.x; f[4*i+1] = v.y; f[4*i+2] = v.z; f[4*i+3] = v.w;
            }
            float sq = 0.f;
#pragma unroll
            for (int i = 0; i < 32; i++) sq = fmaf(f[i], f[i], sq);
            sq += __shfl_xor_sync(~0u, sq, 1);
            xsq[row] = sq;

#pragma unroll
            for (int s4l = 0; s4l < 2; s4l++) {
                const int s4 = 2 * hf + s4l;
                u32 hi[8], lo[8];
#pragma unroll
                for (int qp = 0; qp < 8; qp++) {
                    float a = f[16*s4l + 2*qp], b = f[16*s4l + 2*qp + 1];
                    __nv_bfloat16 ha = __float2bfloat16(a), hb = __float2bfloat16(b);
                    hi[qp] = bfpack(a, b);
                    lo[qp] = bfpack(a - bf2f(ha), b - bf2f(hb));
                }
                char* ph = SB + A_OFF + (size_t)((0*4+s4)*MCHUNK + row) * 32;
                char* pl = SB + A_OFF + (size_t)((1*4+s4)*MCHUNK + row) * 32;
                *(uint4*)(ph)      = make_uint4(hi[0], hi[1], hi[2], hi[3]);
                *(uint4*)(ph + 16) = make_uint4(hi[4], hi[5], hi[6], hi[7]);
                *(uint4*)(pl)      = make_uint4(lo[0], lo[1], lo[2], lo[3]);
                *(uint4*)(pl + 16) = make_uint4(lo[4], lo[5], lo[6], lo[7]);
            }
        }
        __syncthreads();

        // ---- A fragments (held in regs across all N-tiles)
        const int mrow = w * 16 + g;
        u32 afr[12][4];
#pragma unroll
        for (int t3 = 0; t3 < 3; t3++)
#pragma unroll
            for (int s4 = 0; s4 < 4; s4++) {
                const int ks = t3 * 4 + s4;
                const char* pl = SB + A_OFF + (size_t)((SEGA[t3]*4 + s4) * MCHUNK) * 32;
                afr[ks][0] = *(const u32*)(pl + (mrow)     * 32 + q * 4);
                afr[ks][1] = *(const u32*)(pl + (mrow + 8) * 32 + q * 4);
                afr[ks][2] = *(const u32*)(pl + (mrow)     * 32 + (q + 4) * 4);
                afr[ks][3] = *(const u32*)(pl + (mrow + 8) * 32 + (q + 4) * 4);
            }

        const int   crow0 = row0 + w * 16;
        const float xq0 = xsq[w * 16 + g];
        const float xq1 = xsq[w * 16 + g + 8];
        const float INF = __int_as_float(0x7F800000);
        float b0v = INF, b0v2 = INF, b1v = INF, b1v2 = INF;
        int   b0i = 0, b1i = 0;
        float* stg = (float*)(SB + STG_OFF) + w * (16 * 66);

#pragma unroll 1
        for (int nt = 0; nt < 8; nt++) {
            float c[8][4];
#pragma unroll
            for (int nf = 0; nf < 8; nf++)
                c[nf][0] = c[nf][1] = c[nf][2] = c[nf][3] = 0.f;

#pragma unroll
            for (int t3 = 0; t3 < 3; t3++)
#pragma unroll
                for (int s4 = 0; s4 < 4; s4++) {
                    const int ks = t3 * 4 + s4;
                    const char* bpl = SB + B_OFF +
                        (size_t)((SEGB[t3]*4 + s4) * KCB) * 32;
#pragma unroll
                    for (int nf = 0; nf < 8; nf++) {
                        u64 bp = *(const u64*)(bpl +
                            (size_t)(nt*64 + nf*8 + g) * 32 + q * 8);
                        MMA16816(c[nf], afr[ks], (u32)bp, (u32)(bp >> 32));
                    }
                }

#pragma unroll
            for (int nf = 0; nf < 8; nf++) {
                const int k0 = nt * 64 + nf * 8 + 2 * q;
                float2 es = *(const float2*)(esq + k0);
                float d0 = fmaf(-2.f, c[nf][0], xq0 + es.x);
                float d1 = fmaf(-2.f, c[nf][1], xq0 + es.y);
                float d2 = fmaf(-2.f, c[nf][2], xq1 + es.x);
                float d3 = fmaf(-2.f, c[nf][3], xq1 + es.y);
                // top-2 tracking (ascending k, strict < keeps lowest index)
                if (d0 < b0v) { b0v2 = b0v; b0v = d0; b0i = k0; }
                else if (d0 < b0v2) b0v2 = d0;
                if (d1 < b0v) { b0v2 = b0v; b0v = d1; b0i = k0 + 1; }
                else if (d1 < b0v2) b0v2 = d1;
                if (d2 < b1v) { b1v2 = b1v; b1v = d2; b1i = k0; }
                else if (d2 < b1v2) b1v2 = d2;
                if (d3 < b1v) { b1v2 = b1v; b1v = d3; b1i = k0 + 1; }
                else if (d3 < b1v2) b1v2 = d3;
                *(float2*)(stg + g * 66 + nf * 8 + 2 * q)       = make_float2(d0, d1);
                *(float2*)(stg + (g + 8) * 66 + nf * 8 + 2 * q) = make_float2(d2, d3);
            }
            __syncwarp();
#pragma unroll
            for (int rr = 0; rr < 16; rr++) {
                float2 v = *(const float2*)(stg + rr * 66 + 2 * lane);
                __stcs((float2*)(dist + (size_t)(crow0 + rr) * KCB + nt * 64 + 2 * lane), v);
            }
            __syncwarp();
        }

        // quad merge of top-2 (lowest-index on value ties)
#pragma unroll
        for (int o = 1; o <= 2; o <<= 1) {
            float ov  = __shfl_xor_sync(~0u, b0v, o);
            int   oi  = __shfl_xor_sync(~0u, b0i, o);
            float ov2 = __shfl_xor_sync(~0u, b0v2, o);
            if (ov < b0v || (ov == b0v && oi < b0i)) {
                b0v2 = fminf(b0v, ov2); b0v = ov; b0i = oi;
            } else b0v2 = fminf(b0v2, ov);
            float pv  = __shfl_xor_sync(~0u, b1v, o);
            int   pi  = __shfl_xor_sync(~0u, b1i, o);
            float pv2 = __shfl_xor_sync(~0u, b1v2, o);
            if (pv < b1v || (pv == b1v && pi < b1i)) {
                b1v2 = fminf(b1v, pv2); b1v = pv; b1i = pi;
            } else b1v2 = fminf(b1v2, pv);
        }
        if (q == 0) {
            bks[w*16 + g]     = b0i;  bvs[w*16 + g]     = b0v;
            flg[w*16 + g]     = (b0v2 - b0v < MARGIN) ? 1 : 0;
            bks[w*16 + g + 8] = b1i;  bvs[w*16 + g + 8] = b1v;
            flg[w*16 + g + 8] = (b1v2 - b1v < MARGIN) ? 1 : 0;
        }
        __syncwarp();
        __threadfence_block();    // order dist stores before candidate re-reads

        // ---- exact rescue for near-tie rows (rare)
        for (int rr = 0; rr < 16; rr++) {
            if (!flg[w*16 + rr]) continue;
            const int row = crow0 + rr;
            const float thr = bvs[w*16 + rr] + MARGIN;
            const float xa = __ldg(x + (size_t)row * DIM + lane);
            const float xb = __ldg(x + (size_t)row * DIM + 32 + lane);
            const float xq = xsq[w*16 + rr];
            float bev = INF; int bei = 0x7FFFFFFF;
            for (int j = 0; j < 16; j++) {
                float dv = __ldcg(dist + (size_t)row * KCB + j * 32 + lane);
                u32 m = __ballot_sync(~0u, dv <= thr);
                while (m) {
                    const int src = __ffs(m) - 1; m &= m - 1;
                    const int k = j * 32 + src;
                    float p = fmaf(xa, __ldg(g_ET + (size_t)k * DIM + lane),
                                   xb * __ldg(g_ET + (size_t)k * DIM + 32 + lane));
#pragma unroll
                    for (int o = 16; o > 0; o >>= 1) p += __shfl_xor_sync(~0u, p, o);
                    const float de = fmaf(-2.f, p, xq + esq[k]);
                    if (de < bev) { bev = de; bei = k; }   // ascending k
                }
            }
            if (lane == 0) bks[w*16 + rr] = bei;
        }
        __syncwarp();

        // ---- quant (bit-exact STE), enc one-hot, idx, loss
#pragma unroll 1
        for (int rr = 0; rr < 16; rr++) {
            const int row = crow0 + rr;
            const int bk  = bks[w * 16 + rr];
            const float q0 = __ldg(g_ET + (size_t)bk * DIM + lane);
            const float q1 = __ldg(g_ET + (size_t)bk * DIM + 32 + lane);
            const float a0 = __ldg(x + (size_t)row * DIM + lane);
            const float a1 = __ldg(x + (size_t)row * DIM + 32 + lane);
            __stcs(quant + (size_t)row * DIM + lane,      a0 + (q0 - a0));
            __stcs(quant + (size_t)row * DIM + 32 + lane, a1 + (q1 - a1));
            const float e0 = q0 - a0, e1 = q1 - a1;
            lossAcc += e0 * e0 + e1 * e1;

            float* ep = enc + (size_t)row * KCB + 2 * lane;
#pragma unroll
            for (int g8 = 0; g8 < 8; g8++) {
                const int k0 = 2 * lane + 64 * g8;
                __stcs((float2*)(ep + 64 * g8),
                       make_float2(k0 == bk ? 1.f : 0.f, (k0 + 1) == bk ? 1.f : 0.f));
            }
            if (lane == 0) {
                idxf[row] = (float)bk;
                atomicAdd(&hist[bk], 1);
            }
        }
    }

    // ---- final reductions
#pragma unroll
    for (int o = 16; o > 0; o >>= 1) lossAcc += __shfl_xor_sync(~0u, lossAcc, o);
    __syncthreads();
    if (lane == 0) lred[w] = lossAcc;
    __syncthreads();
    if (tid == 0) {
        float s = 0.f;
#pragma unroll
        for (int i = 0; i < WARPS; i++) s += lred[i];
        atomicAdd(&g_loss, s);
    }
    for (int i = tid; i < KCB; i += NTH)
        if (hist[i]) atomicAdd(&g_cnt[i], hist[i]);
}

// ---------------- finalize ----------------
__global__ void vq_finalize(float* __restrict__ loss_out,
                            float* __restrict__ perp_out,
                            float invN, float invND)
{
    __shared__ float red[16];
    int t = threadIdx.x;  // 512
    float p = (float)g_cnt[t] * invN;
    float v = p * logf(p + 1e-10f);
#pragma unroll
    for (int o = 16; o > 0; o >>= 1) v += __shfl_xor_sync(~0u, v, o);
    if ((t & 31) == 0) red[t >> 5] = v;
    __syncthreads();
    if (t == 0) {
        float s = 0.f;
#pragma unroll
        for (int i = 0; i < 16; i++) s += red[i];
        *perp_out = expf(-s);
        *loss_out = 1.25f * g_loss * invND;
    }
}

// ---------------- launch ----------------
extern "C" void kernel_launch(void* const* d_in, const int* in_sizes, int n_in,
                              void* d_out, int out_size)
{
    const float* x = (const float*)d_in[0];
    const float* E = (const float*)d_in[2];
    const int N = in_sizes[0] / DIM;      // 65536

    float* out = (float*)d_out;
    const size_t q_off    = 0;
    const size_t loss_off = (size_t)N * DIM;
    const size_t perp_off = loss_off + 1;
    const size_t enc_off  = perp_off + 1;
    const size_t idx_off  = enc_off + (size_t)N * KCB;
    const size_t dist_off = idx_off + (size_t)N;

    cudaFuncSetAttribute(vq_main, cudaFuncAttributeMaxDynamicSharedMemorySize,
                         SMEM_BYTES);

    dim3 pgrid(KCB / 32, DIM / 32);
    vq_prep<<<pgrid, dim3(32, 32)>>>(E);
    vq_main<<<GRID, NTH, SMEM_BYTES>>>(x,
                                       out + q_off, out + enc_off,
                                       out + idx_off, out + dist_off, N);
    vq_finalize<<<1, KCB>>>(out + loss_off, out + perp_off,
                            1.0f / (float)N, 1.0f / ((float)N * (float)DIM));
}

// round 12
// speedup vs baseline: 1.2450x; 1.2450x over previous
#include <cuda_runtime.h>
#include <cuda_bf16.h>
#include <math.h>

#define DIM     64
#define KCB     512
#define NTH     256
#define WARPS   8
#define GRID    148
#define MARGIN  3e-3f

typedef unsigned int       u32;
typedef unsigned long long u64;
typedef unsigned short     u16;

// ---------------- device scratch ----------------
__device__ float g_ET[KCB * DIM];   // transposed codebook [K][D] fp32
__device__ float g_loss;
__device__ int   g_cnt[KCB];

// ---------------- smem layout (byte offsets) ----------------
#define B_OFF    0          // [seg2][kstep4] x 512 n x 32B   = 131072
#define A_OFF    131072     // [seg2][kstep4] x 128 m x 32B   = 32768
#define STG_OFF  163840     // 8 warps x 16 rows x 66 floats  = 33792
#define ESQ_OFF  197632     // 512 f
#define XSQ_OFF  199680     // 128 f
#define BKS_OFF  200192     // 128 i
#define HIST_OFF 200704     // 512 i
#define LRED_OFF 202752     // 8 f
#define BVS_OFF  202784     // 128 f
#define FLG_OFF  203296     // 128 i
#define SMEM_BYTES 203808

__device__ __forceinline__ u32 bfpack(float a, float b) {
    __nv_bfloat16 ha = __float2bfloat16(a), hb = __float2bfloat16(b);
    u16 ua = *reinterpret_cast<u16*>(&ha), ub = *reinterpret_cast<u16*>(&hb);
    return (u32)ua | ((u32)ub << 16);
}
__device__ __forceinline__ float bf2f(__nv_bfloat16 h) { return __bfloat162float(h); }

#define MMA16816(c, a, b0v, b1v)                                              \
    asm volatile("mma.sync.aligned.m16n8k16.row.col.f32.bf16.bf16.f32 "       \
        "{%0,%1,%2,%3}, {%4,%5,%6,%7}, {%8,%9}, {%0,%1,%2,%3};"               \
        : "+f"((c)[0]), "+f"((c)[1]), "+f"((c)[2]), "+f"((c)[3])              \
        : "r"((a)[0]), "r"((a)[1]), "r"((a)[2]), "r"((a)[3]),                 \
          "r"(b0v), "r"(b1v))

// ---------------- prep ----------------
__global__ void vq_prep(const float* __restrict__ E) {
    __shared__ float t[32][33];
    const int kb = blockIdx.x * 32, db = blockIdx.y * 32;
    t[threadIdx.y][threadIdx.x] = E[(db + threadIdx.y) * KCB + kb + threadIdx.x];
    __syncthreads();
    g_ET[(kb + threadIdx.y) * DIM + db + threadIdx.x] = t[threadIdx.x][threadIdx.y];
    if (blockIdx.x == 0 && blockIdx.y == 0) {
        int id = threadIdx.y * 32 + threadIdx.x;
        if (id < KCB) g_cnt[id] = 0;
        if (id == 0)  g_loss = 0.f;
    }
}

// ---------------- main: warp-autonomous mma.sync + exact rescue ---------
__global__ void __launch_bounds__(NTH, 1)
vq_main(const float* __restrict__ x,
        float* __restrict__ quant, float* __restrict__ enc,
        float* __restrict__ idxf,  float* __restrict__ dist, int nRows)
{
    extern __shared__ char SB[];
    float* esq  = (float*)(SB + ESQ_OFF);
    float* xsq  = (float*)(SB + XSQ_OFF);
    int*   bks  = (int*)  (SB + BKS_OFF);
    int*   hist = (int*)  (SB + HIST_OFF);
    float* lred = (float*)(SB + LRED_OFF);
    float* bvs  = (float*)(SB + BVS_OFF);
    int*   flg  = (int*)  (SB + FLG_OFF);

    const int tid  = threadIdx.x;
    const int lane = tid & 31;
    const int w    = tid >> 5;
    const int g    = lane >> 2;
    const int q    = lane & 3;

    const int SEGA[3] = { 0, 0, 1 };   // (H,H) (H,L) (L,H)
    const int SEGB[3] = { 0, 1, 0 };

    // ---- B planes + exact esq (block-cooperative, once)
#pragma unroll
    for (int j = 0; j < 2; j++) {
        const int n = tid + j * NTH;
        float f[DIM];
        const float4* er = (const float4*)(g_ET + (size_t)n * DIM);
#pragma unroll
        for (int i = 0; i < 16; i++) {
            float4 v = er[i];
            f[4*i] = v.x; f[4*i+1] = v.y; f[4*i+2] = v.z; f[4*i+3] = v.w;
        }
        float sq = 0.f;
#pragma unroll
        for (int i = 0; i < DIM; i++) sq = fmaf(f[i], f[i], sq);
        esq[n] = sq;

        float r[DIM];
#pragma unroll
        for (int i = 0; i < DIM; i++) {
            __nv_bfloat16 h = __float2bfloat16(f[i]);
            r[i] = f[i] - bf2f(h);
        }
#pragma unroll
        for (int s4 = 0; s4 < 4; s4++)
#pragma unroll
            for (int qq = 0; qq < 4; qq++) {
                const int d0 = 16 * s4 + 2 * qq;
                u64 hp = (u64)bfpack(f[d0], f[d0+1]) |
                         ((u64)bfpack(f[d0+8], f[d0+9]) << 32);
                u64 lp = (u64)bfpack(r[d0], r[d0+1]) |
                         ((u64)bfpack(r[d0+8], r[d0+9]) << 32);
                *(u64*)(SB + B_OFF + ((size_t)((0*4+s4)*KCB + n))*32 + qq*8) = hp;
                *(u64*)(SB + B_OFF + ((size_t)((1*4+s4)*KCB + n))*32 + qq*8) = lp;
            }
    }
    for (int i = tid; i < KCB; i += NTH) hist[i] = 0;
    __syncthreads();    // last block barrier until final reduction

    float lossAcc = 0.f;
    const int nTiles = nRows / 16;                     // 4096
    const float INF = __int_as_float(0x7F800000);

    // ---- warp-autonomous tile loop: warp owns 16 rows per tile
    for (int t = blockIdx.x * WARPS + w; t < nTiles; t += GRID * WARPS) {
        const int row0 = t * 16;

        // ---- A fill (warp-local rows w*16..w*16+15 of the A planes)
        {
            const int r16 = lane >> 1, hf = lane & 1;  // local row, d-half
            const int arow = w * 16 + r16;
            const float4* xr = (const float4*)(x + (size_t)(row0 + r16) * DIM) + hf * 8;
            float f[32];
#pragma unroll
            for (int i = 0; i < 8; i++) {
                float4 v = xr[i];
                f[4*i] = v.x; f[4*i+1] = v.y; f[4*i+2] = v.z; f[4*i+3] = v.w;
            }
            float sq = 0.f;
#pragma unroll
            for (int i = 0; i < 32; i++) sq = fmaf(f[i], f[i], sq);
            sq += __shfl_xor_sync(~0u, sq, 1);
            xsq[arow] = sq;

#pragma unroll
            for (int s4l = 0; s4l < 2; s4l++) {
                const int s4 = 2 * hf + s4l;
                u32 hi[8], lo[8];
#pragma unroll
                for (int qp = 0; qp < 8; qp++) {
                    float a = f[16*s4l + 2*qp], b = f[16*s4l + 2*qp + 1];
                    __nv_bfloat16 ha = __float2bfloat16(a), hb = __float2bfloat16(b);
                    hi[qp] = bfpack(a, b);
                    lo[qp] = bfpack(a - bf2f(ha), b - bf2f(hb));
                }
                char* ph = SB + A_OFF + (size_t)((0*4+s4)*128 + arow) * 32;
                char* pl = SB + A_OFF + (size_t)((1*4+s4)*128 + arow) * 32;
                *(uint4*)(ph)      = make_uint4(hi[0], hi[1], hi[2], hi[3]);
                *(uint4*)(ph + 16) = make_uint4(hi[4], hi[5], hi[6], hi[7]);
                *(uint4*)(pl)      = make_uint4(lo[0], lo[1], lo[2], lo[3]);
                *(uint4*)(pl + 16) = make_uint4(lo[4], lo[5], lo[6], lo[7]);
            }
        }
        __syncwarp();

        // ---- A fragments (regs, reused across all N-tiles)
        const int mrow = w * 16 + g;
        u32 afr[12][4];
#pragma unroll
        for (int t3 = 0; t3 < 3; t3++)
#pragma unroll
            for (int s4 = 0; s4 < 4; s4++) {
                const int ks = t3 * 4 + s4;
                const char* pl = SB + A_OFF + (size_t)((SEGA[t3]*4 + s4) * 128) * 32;
                afr[ks][0] = *(const u32*)(pl + (mrow)     * 32 + q * 4);
                afr[ks][1] = *(const u32*)(pl + (mrow + 8) * 32 + q * 4);
                afr[ks][2] = *(const u32*)(pl + (mrow)     * 32 + (q + 4) * 4);
                afr[ks][3] = *(const u32*)(pl + (mrow + 8) * 32 + (q + 4) * 4);
            }

        const float xq0 = xsq[w * 16 + g];
        const float xq1 = xsq[w * 16 + g + 8];
        float b0v = INF, b0v2 = INF, b1v = INF, b1v2 = INF;
        int   b0i = 0, b1i = 0;
        float* stg = (float*)(SB + STG_OFF) + w * (16 * 66);

#pragma unroll 1
        for (int nt = 0; nt < 8; nt++) {
            float c[8][4];
#pragma unroll
            for (int nf = 0; nf < 8; nf++)
                c[nf][0] = c[nf][1] = c[nf][2] = c[nf][3] = 0.f;

#pragma unroll
            for (int t3 = 0; t3 < 3; t3++)
#pragma unroll
                for (int s4 = 0; s4 < 4; s4++) {
                    const int ks = t3 * 4 + s4;
                    const char* bpl = SB + B_OFF +
                        (size_t)((SEGB[t3]*4 + s4) * KCB) * 32;
#pragma unroll
                    for (int nf = 0; nf < 8; nf++) {
                        u64 bp = *(const u64*)(bpl +
                            (size_t)(nt*64 + nf*8 + g) * 32 + q * 8);
                        MMA16816(c[nf], afr[ks], (u32)bp, (u32)(bp >> 32));
                    }
                }

#pragma unroll
            for (int nf = 0; nf < 8; nf++) {
                const int k0 = nt * 64 + nf * 8 + 2 * q;
                float2 es = *(const float2*)(esq + k0);
                float d0 = fmaf(-2.f, c[nf][0], xq0 + es.x);
                float d1 = fmaf(-2.f, c[nf][1], xq0 + es.y);
                float d2 = fmaf(-2.f, c[nf][2], xq1 + es.x);
                float d3 = fmaf(-2.f, c[nf][3], xq1 + es.y);
                if (d0 < b0v) { b0v2 = b0v; b0v = d0; b0i = k0; }
                else if (d0 < b0v2) b0v2 = d0;
                if (d1 < b0v) { b0v2 = b0v; b0v = d1; b0i = k0 + 1; }
                else if (d1 < b0v2) b0v2 = d1;
                if (d2 < b1v) { b1v2 = b1v; b1v = d2; b1i = k0; }
                else if (d2 < b1v2) b1v2 = d2;
                if (d3 < b1v) { b1v2 = b1v; b1v = d3; b1i = k0 + 1; }
                else if (d3 < b1v2) b1v2 = d3;
                *(float2*)(stg + g * 66 + nf * 8 + 2 * q)       = make_float2(d0, d1);
                *(float2*)(stg + (g + 8) * 66 + nf * 8 + 2 * q) = make_float2(d2, d3);
            }
            __syncwarp();
#pragma unroll
            for (int rr = 0; rr < 16; rr++) {
                float2 v = *(const float2*)(stg + rr * 66 + 2 * lane);
                __stcs((float2*)(dist + (size_t)(row0 + rr) * KCB + nt * 64 + 2 * lane), v);
            }
            __syncwarp();
        }

        // quad merge of top-2 (lowest-index on value ties)
#pragma unroll
        for (int o = 1; o <= 2; o <<= 1) {
            float ov  = __shfl_xor_sync(~0u, b0v, o);
            int   oi  = __shfl_xor_sync(~0u, b0i, o);
            float ov2 = __shfl_xor_sync(~0u, b0v2, o);
            if (ov < b0v || (ov == b0v && oi < b0i)) {
                b0v2 = fminf(b0v, ov2); b0v = ov; b0i = oi;
            } else b0v2 = fminf(b0v2, ov);
            float pv  = __shfl_xor_sync(~0u, b1v, o);
            int   pi  = __shfl_xor_sync(~0u, b1i, o);
            float pv2 = __shfl_xor_sync(~0u, b1v2, o);
            if (pv < b1v || (pv == b1v && pi < b1i)) {
                b1v2 = fminf(b1v, pv2); b1v = pv; b1i = pi;
            } else b1v2 = fminf(b1v2, pv);
        }
        if (q == 0) {
            bks[w*16 + g]     = b0i;  bvs[w*16 + g]     = b0v;
            flg[w*16 + g]     = (b0v2 - b0v < MARGIN) ? 1 : 0;
            bks[w*16 + g + 8] = b1i;  bvs[w*16 + g + 8] = b1v;
            flg[w*16 + g + 8] = (b1v2 - b1v < MARGIN) ? 1 : 0;
        }
        __syncwarp();
        __threadfence_block();

        // ---- exact rescue for near-tie rows (rare)
        for (int rr = 0; rr < 16; rr++) {
            if (!flg[w*16 + rr]) continue;
            const int row = row0 + rr;
            const float thr = bvs[w*16 + rr] + MARGIN;
            const float xa = __ldg(x + (size_t)row * DIM + lane);
            const float xb = __ldg(x + (size_t)row * DIM + 32 + lane);
            const float xq = xsq[w*16 + rr];
            float bev = INF; int bei = 0x7FFFFFFF;
            for (int j = 0; j < 16; j++) {
                float dv = __ldcg(dist + (size_t)row * KCB + j * 32 + lane);
                u32 m = __ballot_sync(~0u, dv <= thr);
                while (m) {
                    const int src = __ffs(m) - 1; m &= m - 1;
                    const int k = j * 32 + src;
                    float p = fmaf(xa, __ldg(g_ET + (size_t)k * DIM + lane),
                                   xb * __ldg(g_ET + (size_t)k * DIM + 32 + lane));
#pragma unroll
                    for (int o = 16; o > 0; o >>= 1) p += __shfl_xor_sync(~0u, p, o);
                    const float de = fmaf(-2.f, p, xq + esq[k]);
                    if (de < bev) { bev = de; bei = k; }
                }
            }
            if (lane == 0) bks[w*16 + rr] = bei;
        }
        __syncwarp();

        // ---- quant (bit-exact STE), enc, idx, loss — 4-row batches, MLP=16
#pragma unroll 1
        for (int rb = 0; rb < 16; rb += 4) {
            int bk4[4]; float q0[4], q1[4], a0[4], a1[4];
#pragma unroll
            for (int j = 0; j < 4; j++) {
                const int rr = rb + j;
                bk4[j] = bks[w * 16 + rr];
                const int row = row0 + rr;
                q0[j] = __ldg(g_ET + (size_t)bk4[j] * DIM + lane);
                q1[j] = __ldg(g_ET + (size_t)bk4[j] * DIM + 32 + lane);
                a0[j] = __ldg(x + (size_t)row * DIM + lane);
                a1[j] = __ldg(x + (size_t)row * DIM + 32 + lane);
            }
#pragma unroll
            for (int j = 0; j < 4; j++) {
                const int row = row0 + rb + j;
                const int bk  = bk4[j];
                __stcs(quant + (size_t)row * DIM + lane,      a0[j] + (q0[j] - a0[j]));
                __stcs(quant + (size_t)row * DIM + 32 + lane, a1[j] + (q1[j] - a1[j]));
                const float e0 = q0[j] - a0[j], e1 = q1[j] - a1[j];
                lossAcc += e0 * e0 + e1 * e1;

                float* ep = enc + (size_t)row * KCB + 2 * lane;
#pragma unroll
                for (int g8 = 0; g8 < 8; g8++) {
                    const int k0 = 2 * lane + 64 * g8;
                    __stcs((float2*)(ep + 64 * g8),
                           make_float2(k0 == bk ? 1.f : 0.f, (k0 + 1) == bk ? 1.f : 0.f));
                }
                if (lane == 0) {
                    idxf[row] = (float)bk;
                    atomicAdd(&hist[bk], 1);
                }
            }
        }
    }

    // ---- final reductions
#pragma unroll
    for (int o = 16; o > 0; o >>= 1) lossAcc += __shfl_xor_sync(~0u, lossAcc, o);
    __syncthreads();
    if (lane == 0) lred[w] = lossAcc;
    __syncthreads();
    if (tid == 0) {
        float s = 0.f;
#pragma unroll
        for (int i = 0; i < WARPS; i++) s += lred[i];
        atomicAdd(&g_loss, s);
    }
    for (int i = tid; i < KCB; i += NTH)
        if (hist[i]) atomicAdd(&g_cnt[i], hist[i]);
}

// ---------------- finalize ----------------
__global__ void vq_finalize(float* __restrict__ loss_out,
                            float* __restrict__ perp_out,
                            float invN, float invND)
{
    __shared__ float red[16];
    int t = threadIdx.x;  // 512
    float p = (float)g_cnt[t] * invN;
    float v = p * logf(p + 1e-10f);
#pragma unroll
    for (int o = 16; o > 0; o >>= 1) v += __shfl_xor_sync(~0u, v, o);
    if ((t & 31) == 0) red[t >> 5] = v;
    __syncthreads();
    if (t == 0) {
        float s = 0.f;
#pragma unroll
        for (int i = 0; i < 16; i++) s += red[i];
        *perp_out = expf(-s);
        *loss_out = 1.25f * g_loss * invND;
    }
}

// ---------------- launch ----------------
extern "C" void kernel_launch(void* const* d_in, const int* in_sizes, int n_in,
                              void* d_out, int out_size)
{
    const float* x = (const float*)d_in[0];
    const float* E = (const float*)d_in[2];
    const int N = in_sizes[0] / DIM;      // 65536

    float* out = (float*)d_out;
    const size_t q_off    = 0;
    const size_t loss_off = (size_t)N * DIM;
    const size_t perp_off = loss_off + 1;
    const size_t enc_off  = perp_off + 1;
    const size_t idx_off  = enc_off + (size_t)N * KCB;
    const size_t dist_off = idx_off + (size_t)N;

    cudaFuncSetAttribute(vq_main, cudaFuncAttributeMaxDynamicSharedMemorySize,
                         SMEM_BYTES);

    dim3 pgrid(KCB / 32, DIM / 32);
    vq_prep<<<pgrid, dim3(32, 32)>>>(E);
    vq_main<<<GRID, NTH, SMEM_BYTES>>>(x,
                                       out + q_off, out + enc_off,
                                       out + idx_off, out + dist_off, N);
    vq_finalize<<<1, KCB>>>(out + loss_off, out + perp_off,
                            1.0f / (float)N, 1.0f / ((float)N * (float)DIM));
}